// round 1
// baseline (speedup 1.0000x reference)
#include <cuda_runtime.h>

#define BATCH 4
#define SEQ   2048
#define DIN   1024
#define HEADS 8
#define UNITS 128

// Scratch (device globals: allocation inside kernel_launch is forbidden)
__device__ float g_q[BATCH*HEADS*SEQ*UNITS];
__device__ float g_k[BATCH*HEADS*SEQ*UNITS];
__device__ float g_v[BATCH*HEADS*SEQ*UNITS];
__device__ float g_flat[BATCH*SEQ*HEADS*UNITS];

// ---------------------------------------------------------------------------
// QKV projection: out[b,h,s,u] = sum_d x[b,s,d] * W[h,d,u] + bias[h,u]
// One block computes a 128x128 tile (128 rows of x, all 128 units of one head
// of one projection). blockIdx.y in [0,24): proj = y>>3, head = y&7.
// ---------------------------------------------------------------------------
__global__ __launch_bounds__(256) void qkv_gemm_kernel(
    const float* __restrict__ x,
    const float* __restrict__ wq, const float* __restrict__ wk, const float* __restrict__ wv,
    const float* __restrict__ bq, const float* __restrict__ bk, const float* __restrict__ bv)
{
    __shared__ float As[16][128];   // A tile, stored transposed: As[k][row]
    __shared__ float Bsh[16][128];  // B tile: Bsh[k][col]

    const int tid = threadIdx.x;
    const int tm  = tid >> 4;       // 0..15
    const int tn  = tid & 15;       // 0..15
    const int rowTile = blockIdx.x; // 0..63
    const int proj = blockIdx.y >> 3;
    const int h    = blockIdx.y & 7;

    const float* W     = (proj == 0 ? wq : (proj == 1 ? wk : wv)) + (size_t)h * DIN * UNITS;
    const float* biasp = (proj == 0 ? bq : (proj == 1 ? bk : bv)) + h * UNITS;
    float* outbase     = (proj == 0 ? g_q : (proj == 1 ? g_k : g_v));

    const float* A = x + (size_t)rowTile * 128 * DIN;

    float acc[8][8];
    #pragma unroll
    for (int i = 0; i < 8; i++)
        #pragma unroll
        for (int j = 0; j < 8; j++) acc[i][j] = 0.f;

    for (int k0 = 0; k0 < DIN; k0 += 16) {
        // Load A tile: 128 rows x 16 cols, transpose into As[k][row]
        #pragma unroll
        for (int i = 0; i < 2; i++) {
            int idx = tid + i*256;           // 0..511
            int r   = idx >> 2;              // 0..127
            int c4  = idx & 3;               // 0..3 (float4 within 16 cols)
            float4 v = *(const float4*)(A + (size_t)r * DIN + k0 + c4*4);
            As[c4*4+0][r] = v.x;
            As[c4*4+1][r] = v.y;
            As[c4*4+2][r] = v.z;
            As[c4*4+3][r] = v.w;
        }
        // Load B tile: 16 rows x 128 cols (row-major, perfectly coalesced)
        #pragma unroll
        for (int i = 0; i < 2; i++) {
            int idx = tid + i*256;
            int r   = idx >> 5;              // 0..15
            int c4  = idx & 31;              // 0..31
            *(float4*)&Bsh[r][c4*4] = *(const float4*)(W + (size_t)(k0+r)*UNITS + c4*4);
        }
        __syncthreads();

        #pragma unroll
        for (int k = 0; k < 16; k++) {
            float4 a0 = *(const float4*)&As[k][tm*8];
            float4 a1 = *(const float4*)&As[k][tm*8+4];
            float4 b0 = *(const float4*)&Bsh[k][tn*8];
            float4 b1 = *(const float4*)&Bsh[k][tn*8+4];
            float av[8] = {a0.x,a0.y,a0.z,a0.w,a1.x,a1.y,a1.z,a1.w};
            float bw[8] = {b0.x,b0.y,b0.z,b0.w,b1.x,b1.y,b1.z,b1.w};
            #pragma unroll
            for (int i = 0; i < 8; i++)
                #pragma unroll
                for (int j = 0; j < 8; j++)
                    acc[i][j] += av[i]*bw[j];
        }
        __syncthreads();
    }

    float bias0[8];
    #pragma unroll
    for (int j = 0; j < 8; j++) bias0[j] = biasp[tn*8+j];

    #pragma unroll
    for (int i = 0; i < 8; i++) {
        int r = rowTile*128 + tm*8 + i;      // global row in [0, 8192)
        int b = r >> 11;                     // / SEQ
        int s = r & (SEQ-1);
        float* orow = outbase + (((size_t)(b*HEADS + h))*SEQ + s)*UNITS + tn*8;
        float4 o0 = make_float4(acc[i][0]+bias0[0], acc[i][1]+bias0[1],
                                acc[i][2]+bias0[2], acc[i][3]+bias0[3]);
        float4 o1 = make_float4(acc[i][4]+bias0[4], acc[i][5]+bias0[5],
                                acc[i][6]+bias0[6], acc[i][7]+bias0[7]);
        *(float4*)(orow)   = o0;
        *(float4*)(orow+4) = o1;
    }
}

// ---------------------------------------------------------------------------
// Flash attention (no mask), fp32, online softmax.
// Block: 64 Q rows of one (b,h). 256 threads: ri = tid>>4 owns rows ri*4..+3,
// ci = tid&15 owns score cols ci*4..+3 and output cols ci*8..+7.
// Q and K tiles stored d-major (transposed) with XOR swizzle for conflict-free
// LDS.128 in the score loop; V stored row-major in the same (aliased) buffer.
// ---------------------------------------------------------------------------
__global__ __launch_bounds__(256) void attn_kernel()
{
    extern __shared__ float smem[];
    float* Qs = smem;                 // 128*64 = 8192 floats (d-major, swizzled)
    float* KV = smem + 8192;          // max(128*64, 64*132) = 8448 floats
    float* Ps = smem + 8192 + 8448;   // 64*68 = 4352 floats
    // total 20992 floats = 83968 bytes

    const int tid = threadIdx.x;
    const int ri  = tid >> 4;
    const int ci  = tid & 15;
    const int ri4 = ri * 4;
    const int ci4 = ci * 4;
    const int qb  = blockIdx.x;       // 0..31 (q tile)
    const int bh  = blockIdx.y;       // 0..31
    const int b   = bh >> 3;
    const int h   = bh & 7;

    const float* Qg = g_q + ((size_t)bh * SEQ + qb*64) * UNITS;
    const float* Kg = g_k + (size_t)bh * SEQ * UNITS;
    const float* Vg = g_v + (size_t)bh * SEQ * UNITS;

    const float qscale = 0.08838834764831845f;  // 1/sqrt(128)

    // Load Q tile (64x128), transpose+swizzle+scale into Qs[d*64 + (row^sw)]
    #pragma unroll
    for (int i = 0; i < 8; i++) {
        int idx = tid + i*256;        // 0..2047
        int row = idx >> 5;           // 0..63
        int c4  = idx & 31;           // 0..31
        float4 v = *(const float4*)(Qg + row*UNITS + c4*4);
        int d  = c4*4;
        int r2 = row ^ ((c4 & 15) << 2);
        Qs[(d+0)*64 + r2] = v.x * qscale;
        Qs[(d+1)*64 + r2] = v.y * qscale;
        Qs[(d+2)*64 + r2] = v.z * qscale;
        Qs[(d+3)*64 + r2] = v.w * qscale;
    }

    float m[4], l[4], acc[4][8];
    #pragma unroll
    for (int r = 0; r < 4; r++) {
        m[r] = -1e30f;
        l[r] = 0.f;
        #pragma unroll
        for (int c = 0; c < 8; c++) acc[r][c] = 0.f;
    }
    __syncthreads();

    for (int kt = 0; kt < SEQ/64; kt++) {
        // ---- Load K tile (64x128) transposed+swizzled into KV ----
        const float* Kt = Kg + (size_t)kt*64*UNITS;
        #pragma unroll
        for (int i = 0; i < 8; i++) {
            int idx = tid + i*256;
            int row = idx >> 5;
            int c4  = idx & 31;
            float4 v = *(const float4*)(Kt + row*UNITS + c4*4);
            int d  = c4*4;
            int r2 = row ^ ((c4 & 15) << 2);
            KV[(d+0)*64 + r2] = v.x;
            KV[(d+1)*64 + r2] = v.y;
            KV[(d+2)*64 + r2] = v.z;
            KV[(d+3)*64 + r2] = v.w;
        }
        __syncthreads();

        // ---- Scores: s[r][c] = sum_d Qs[d][ri4+r] * Ks[d][ci4+c] ----
        float s[4][4];
        #pragma unroll
        for (int r = 0; r < 4; r++)
            #pragma unroll
            for (int c = 0; c < 4; c++) s[r][c] = 0.f;

        #pragma unroll 16
        for (int d = 0; d < 128; d++) {
            int sw = ((d >> 2) & 15) << 2;
            float4 qf = *(const float4*)&Qs[d*64 + (ri4 ^ sw)];
            float4 kf = *(const float4*)&KV[d*64 + (ci4 ^ sw)];
            float qv[4] = {qf.x, qf.y, qf.z, qf.w};
            float kv[4] = {kf.x, kf.y, kf.z, kf.w};
            #pragma unroll
            for (int r = 0; r < 4; r++)
                #pragma unroll
                for (int c = 0; c < 4; c++)
                    s[r][c] += qv[r]*kv[c];
        }

        // ---- Online softmax update ----
        float mt[4], mn[4], alpha[4], rs[4];
        #pragma unroll
        for (int r = 0; r < 4; r++)
            mt[r] = fmaxf(fmaxf(s[r][0], s[r][1]), fmaxf(s[r][2], s[r][3]));
        #pragma unroll
        for (int off = 8; off > 0; off >>= 1) {
            #pragma unroll
            for (int r = 0; r < 4; r++)
                mt[r] = fmaxf(mt[r], __shfl_xor_sync(0xffffffffu, mt[r], off));
        }
        #pragma unroll
        for (int r = 0; r < 4; r++) {
            mn[r]    = fmaxf(m[r], mt[r]);
            alpha[r] = __expf(m[r] - mn[r]);
        }
        #pragma unroll
        for (int r = 0; r < 4; r++) {
            float p0 = __expf(s[r][0] - mn[r]);
            float p1 = __expf(s[r][1] - mn[r]);
            float p2 = __expf(s[r][2] - mn[r]);
            float p3 = __expf(s[r][3] - mn[r]);
            *(float4*)&Ps[(ri4+r)*68 + ci4] = make_float4(p0, p1, p2, p3);
            rs[r] = (p0+p1) + (p2+p3);
        }
        #pragma unroll
        for (int off = 8; off > 0; off >>= 1) {
            #pragma unroll
            for (int r = 0; r < 4; r++)
                rs[r] += __shfl_xor_sync(0xffffffffu, rs[r], off);
        }
        #pragma unroll
        for (int r = 0; r < 4; r++) {
            l[r] = l[r]*alpha[r] + rs[r];
            m[r] = mn[r];
            #pragma unroll
            for (int c = 0; c < 8; c++) acc[r][c] *= alpha[r];
        }
        __syncthreads();   // Ps fully written; everyone done reading K

        // ---- Load V tile (64x128) row-major into the same buffer ----
        const float* Vt = Vg + (size_t)kt*64*UNITS;
        #pragma unroll
        for (int i = 0; i < 8; i++) {
            int idx = tid + i*256;
            int row = idx >> 5;
            int c4  = idx & 31;
            *(float4*)&KV[row*132 + c4*4] = *(const float4*)(Vt + row*UNITS + c4*4);
        }
        __syncthreads();

        // ---- acc[r][c] += sum_kk P[ri4+r][kk] * V[kk][ci*8+c] ----
        #pragma unroll 4
        for (int kk = 0; kk < 64; kk++) {
            float p[4];
            #pragma unroll
            for (int r = 0; r < 4; r++) p[r] = Ps[(ri4+r)*68 + kk];
            float4 v0 = *(const float4*)&KV[kk*132 + ci*8];
            float4 v1 = *(const float4*)&KV[kk*132 + ci*8 + 4];
            float vv[8] = {v0.x, v0.y, v0.z, v0.w, v1.x, v1.y, v1.z, v1.w};
            #pragma unroll
            for (int r = 0; r < 4; r++)
                #pragma unroll
                for (int c = 0; c < 8; c++)
                    acc[r][c] += p[r]*vv[c];
        }
        __syncthreads();   // before next tile overwrites KV
    }

    // ---- Normalize and write in flat [B, S, H*U] layout ----
    #pragma unroll
    for (int r = 0; r < 4; r++) {
        float inv = 1.0f / l[r];
        int sg = qb*64 + ri4 + r;
        float* orow = g_flat + ((size_t)b*SEQ + sg)*(HEADS*UNITS) + h*UNITS + ci*8;
        float4 o0 = make_float4(acc[r][0]*inv, acc[r][1]*inv, acc[r][2]*inv, acc[r][3]*inv);
        float4 o1 = make_float4(acc[r][4]*inv, acc[r][5]*inv, acc[r][6]*inv, acc[r][7]*inv);
        *(float4*)(orow)   = o0;
        *(float4*)(orow+4) = o1;
    }
}

// ---------------------------------------------------------------------------
// Output projection: out[r, u'] = sum_k flat[r, k] * Wh[k, u'] + bias[u']
// r in [0, 8192), k in [0, 1024), u' in [0, 128). Same tiling as qkv_gemm.
// ---------------------------------------------------------------------------
__global__ __launch_bounds__(256) void out_gemm_kernel(
    const float* __restrict__ Wh, const float* __restrict__ hbias,
    float* __restrict__ out)
{
    __shared__ float As[16][128];
    __shared__ float Bsh[16][128];

    const int tid = threadIdx.x;
    const int tm  = tid >> 4;
    const int tn  = tid & 15;
    const int rowTile = blockIdx.x;

    const float* A = g_flat + (size_t)rowTile * 128 * (HEADS*UNITS);

    float acc[8][8];
    #pragma unroll
    for (int i = 0; i < 8; i++)
        #pragma unroll
        for (int j = 0; j < 8; j++) acc[i][j] = 0.f;

    for (int k0 = 0; k0 < HEADS*UNITS; k0 += 16) {
        #pragma unroll
        for (int i = 0; i < 2; i++) {
            int idx = tid + i*256;
            int r   = idx >> 2;
            int c4  = idx & 3;
            float4 v = *(const float4*)(A + (size_t)r * (HEADS*UNITS) + k0 + c4*4);
            As[c4*4+0][r] = v.x;
            As[c4*4+1][r] = v.y;
            As[c4*4+2][r] = v.z;
            As[c4*4+3][r] = v.w;
        }
        #pragma unroll
        for (int i = 0; i < 2; i++) {
            int idx = tid + i*256;
            int r   = idx >> 5;
            int c4  = idx & 31;
            *(float4*)&Bsh[r][c4*4] = *(const float4*)(Wh + (size_t)(k0+r)*UNITS + c4*4);
        }
        __syncthreads();

        #pragma unroll
        for (int k = 0; k < 16; k++) {
            float4 a0 = *(const float4*)&As[k][tm*8];
            float4 a1 = *(const float4*)&As[k][tm*8+4];
            float4 b0 = *(const float4*)&Bsh[k][tn*8];
            float4 b1 = *(const float4*)&Bsh[k][tn*8+4];
            float av[8] = {a0.x,a0.y,a0.z,a0.w,a1.x,a1.y,a1.z,a1.w};
            float bw[8] = {b0.x,b0.y,b0.z,b0.w,b1.x,b1.y,b1.z,b1.w};
            #pragma unroll
            for (int i = 0; i < 8; i++)
                #pragma unroll
                for (int j = 0; j < 8; j++)
                    acc[i][j] += av[i]*bw[j];
        }
        __syncthreads();
    }

    float bias0[8];
    #pragma unroll
    for (int j = 0; j < 8; j++) bias0[j] = hbias[tn*8+j];

    #pragma unroll
    for (int i = 0; i < 8; i++) {
        int r = rowTile*128 + tm*8 + i;
        float* orow = out + (size_t)r*UNITS + tn*8;
        float4 o0 = make_float4(acc[i][0]+bias0[0], acc[i][1]+bias0[1],
                                acc[i][2]+bias0[2], acc[i][3]+bias0[3]);
        float4 o1 = make_float4(acc[i][4]+bias0[4], acc[i][5]+bias0[5],
                                acc[i][6]+bias0[6], acc[i][7]+bias0[7]);
        *(float4*)(orow)   = o0;
        *(float4*)(orow+4) = o1;
    }
}

// ---------------------------------------------------------------------------
extern "C" void kernel_launch(void* const* d_in, const int* in_sizes, int n_in,
                              void* d_out, int out_size)
{
    (void)in_sizes; (void)n_in; (void)out_size;
    const float* x   = (const float*)d_in[0];
    const float* wq  = (const float*)d_in[1];
    const float* wk  = (const float*)d_in[2];
    const float* wv  = (const float*)d_in[3];
    const float* bq  = (const float*)d_in[4];
    const float* bk  = (const float*)d_in[5];
    const float* bv  = (const float*)d_in[6];
    const float* wh  = (const float*)d_in[7];
    const float* bh  = (const float*)d_in[8];
    float* out = (float*)d_out;

    const int attn_smem = 20992 * (int)sizeof(float);  // 83968 bytes
    cudaFuncSetAttribute(attn_kernel, cudaFuncAttributeMaxDynamicSharedMemorySize, attn_smem);

    qkv_gemm_kernel<<<dim3(BATCH*SEQ/128, 24), 256>>>(x, wq, wk, wv, bq, bk, bv);
    attn_kernel<<<dim3(SEQ/64, BATCH*HEADS), 256, attn_smem>>>();
    out_gemm_kernel<<<dim3(BATCH*SEQ/128, 1), 256>>>(wh, bh, out);
}

// round 3
// speedup vs baseline: 2.5642x; 2.5642x over previous
#include <cuda_runtime.h>
#include <cstdint>

#define BATCH 4
#define SEQ   2048
#define DIN   1024
#define HEADS 8
#define UNITS 128

// Scratch (device globals: allocation inside kernel_launch is forbidden)
__device__ float g_q[BATCH*HEADS*SEQ*UNITS];
__device__ float g_k[BATCH*HEADS*SEQ*UNITS];
__device__ float g_v[BATCH*HEADS*SEQ*UNITS];
__device__ float g_flat[BATCH*SEQ*HEADS*UNITS];
// 25 transposed weight matrices, each [128 n][1024 k], tf32-rounded.
// g 0..7 = Q heads, 8..15 = K heads, 16..23 = V heads, 24 = head_kernel.
__device__ float g_wt[25*128*1024];

// ---------------------------------------------------------------------------
// Helpers (sm_80-level PTX only: must compile for compute_103 virtual arch)
// ---------------------------------------------------------------------------
__device__ __forceinline__ float f2tf32(float x) {
    uint32_t r;
    asm("cvt.rn.tf32.f32 %0, %1;" : "=r"(r) : "f"(x));
    return __uint_as_float(r);
}
__device__ __forceinline__ uint32_t fbits(float x) { return __float_as_uint(x); }

__device__ __forceinline__ void mma8(float* c,
                                     uint32_t a0, uint32_t a1, uint32_t a2, uint32_t a3,
                                     uint32_t b0, uint32_t b1) {
    asm volatile(
        "mma.sync.aligned.m16n8k8.row.col.f32.tf32.tf32.f32 "
        "{%0,%1,%2,%3}, {%4,%5,%6,%7}, {%8,%9}, {%0,%1,%2,%3};"
        : "+f"(c[0]), "+f"(c[1]), "+f"(c[2]), "+f"(c[3])
        : "r"(a0), "r"(a1), "r"(a2), "r"(a3), "r"(b0), "r"(b1));
}

// ---------------------------------------------------------------------------
// Weight transpose + tf32 rounding: g_wt[g][n][k] = round_tf32(W_g[k][n])
// ---------------------------------------------------------------------------
__global__ __launch_bounds__(256) void transpose_w_kernel(
    const float* __restrict__ wq, const float* __restrict__ wk,
    const float* __restrict__ wv, const float* __restrict__ wh)
{
    __shared__ float t[32][33];
    const int g  = blockIdx.z;
    const int kb = blockIdx.x * 32;
    const int nb = blockIdx.y * 32;
    const int tx = threadIdx.x, ty = threadIdx.y;

    const float* W = (g < 8)  ? wq + (size_t)g * 131072
                   : (g < 16) ? wk + (size_t)(g - 8) * 131072
                   : (g < 24) ? wv + (size_t)(g - 16) * 131072
                              : wh;
    #pragma unroll
    for (int j = 0; j < 4; j++)
        t[ty + j*8][tx] = W[(size_t)(kb + ty + j*8) * 128 + nb + tx];
    __syncthreads();
    float* outp = g_wt + (size_t)g * 131072;
    #pragma unroll
    for (int j = 0; j < 4; j++)
        outp[(size_t)(nb + ty + j*8) * 1024 + kb + tx] = f2tf32(t[tx][ty + j*8]);
}

// ---------------------------------------------------------------------------
// tf32 mma.sync GEMM: C[128-row tile of M=8192, 128] = A[.,1024] x B^T + bias
// mode 0: A = x, 24 GEMMs (blockIdx.y = proj*8+head), out -> g_q/g_k/g_v
// mode 1: A = g_flat, B = g_wt[24], out -> out1
// 256 threads = 8 warps (2M x 4N), warp tile 64x32. K chunks of 32, dbl-buf.
// smem stride 36 floats => A-frag & B-frag scalar LDS conflict-free.
// ---------------------------------------------------------------------------
__global__ __launch_bounds__(256) void gemm_mma_kernel(
    const float* __restrict__ Ain, int mode,
    const float* __restrict__ bq, const float* __restrict__ bk,
    const float* __restrict__ bv, const float* __restrict__ bhp,
    float* __restrict__ out1)
{
    extern __shared__ float sm[];
    float* As = sm;                 // [2][128][36]
    float* Bs = sm + 2*128*36;      // [2][128][36]
    __shared__ float sBias[128];

    const int tid   = threadIdx.x;
    const int w     = tid >> 5;
    const int lane  = tid & 31;
    const int quad  = lane >> 2;    // 0..7
    const int qt    = lane & 3;     // 0..3
    const int wm    = w >> 2;       // 0..1
    const int wn    = w & 3;        // 0..3
    const int mtile = blockIdx.x;
    const int g     = blockIdx.y;
    const int proj  = g >> 3;
    const int head  = g & 7;

    const float* A = (mode == 0) ? Ain : g_flat;
    const float* B = g_wt + (size_t)((mode == 0) ? g : 24) * 131072;
    const float* bias = (mode == 0)
        ? ((proj == 0 ? bq : proj == 1 ? bk : bv) + head * 128)
        : bhp;
    if (tid < 128) sBias[tid] = bias[tid];

    const float* Abase = A + (size_t)mtile * 128 * 1024;

    float acc[4][4][4];
    #pragma unroll
    for (int i = 0; i < 4; i++)
        #pragma unroll
        for (int j = 0; j < 4; j++)
            #pragma unroll
            for (int e = 0; e < 4; e++) acc[i][j][e] = 0.f;

    // chunk loader: 128 rows x 32 cols into buffer buf (A with tf32 cvt, B raw)
    auto load_chunk = [&](int c, int buf) {
        const int k0 = c * 32;
        float* Ad = As + buf * 128*36;
        float* Bd = Bs + buf * 128*36;
        #pragma unroll
        for (int i = 0; i < 4; i++) {
            int idx = i * 256 + tid;       // 0..1023
            int row = idx >> 3;            // 0..127
            int c4  = idx & 7;             // 0..7
            float4 v = *(const float4*)(Abase + (size_t)row * 1024 + k0 + c4 * 4);
            v.x = f2tf32(v.x); v.y = f2tf32(v.y); v.z = f2tf32(v.z); v.w = f2tf32(v.w);
            *(float4*)(Ad + row * 36 + c4 * 4) = v;
        }
        #pragma unroll
        for (int i = 0; i < 4; i++) {
            int idx = i * 256 + tid;
            int row = idx >> 3;
            int c4  = idx & 7;
            *(float4*)(Bd + row * 36 + c4 * 4) =
                *(const float4*)(B + (size_t)row * 1024 + k0 + c4 * 4);
        }
    };

    load_chunk(0, 0);

    const int NCH = 32;
    for (int c = 0; c < NCH; c++) {
        __syncthreads();
        if (c + 1 < NCH) load_chunk(c + 1, (c + 1) & 1);

        const float* Ab = As + (c & 1) * 128*36;
        const float* Bb = Bs + (c & 1) * 128*36;

        #pragma unroll
        for (int ks = 0; ks < 4; ks++) {
            uint32_t af[4][4];
            #pragma unroll
            for (int mf = 0; mf < 4; mf++) {
                int r = wm*64 + mf*16 + quad;
                af[mf][0] = fbits(Ab[r      *36 + ks*8 + qt]);
                af[mf][1] = fbits(Ab[(r + 8)*36 + ks*8 + qt]);
                af[mf][2] = fbits(Ab[r      *36 + ks*8 + 4 + qt]);
                af[mf][3] = fbits(Ab[(r + 8)*36 + ks*8 + 4 + qt]);
            }
            #pragma unroll
            for (int nf = 0; nf < 4; nf++) {
                int n = wn*32 + nf*8 + quad;
                uint32_t b0 = fbits(Bb[n*36 + ks*8 + qt]);
                uint32_t b1 = fbits(Bb[n*36 + ks*8 + 4 + qt]);
                #pragma unroll
                for (int mf = 0; mf < 4; mf++)
                    mma8(acc[mf][nf], af[mf][0], af[mf][1], af[mf][2], af[mf][3], b0, b1);
            }
        }
    }
    __syncthreads();

    // epilogue
    #pragma unroll
    for (int mf = 0; mf < 4; mf++) {
        int rl0 = wm*64 + mf*16 + quad;
        int R0  = mtile*128 + rl0;
        int R1  = R0 + 8;
        float *orow0, *orow1;
        if (mode == 0) {
            float* ob = (proj == 0) ? g_q : (proj == 1) ? g_k : g_v;
            int b0i = R0 >> 11, s0 = R0 & 2047;
            int b1i = R1 >> 11, s1 = R1 & 2047;
            orow0 = ob + (((size_t)(b0i*8 + head))*2048 + s0)*128;
            orow1 = ob + (((size_t)(b1i*8 + head))*2048 + s1)*128;
        } else {
            orow0 = out1 + (size_t)R0 * 128;
            orow1 = out1 + (size_t)R1 * 128;
        }
        #pragma unroll
        for (int nf = 0; nf < 4; nf++) {
            int c0 = wn*32 + nf*8 + qt*2;
            float2 v0 = make_float2(acc[mf][nf][0] + sBias[c0], acc[mf][nf][1] + sBias[c0+1]);
            float2 v1 = make_float2(acc[mf][nf][2] + sBias[c0], acc[mf][nf][3] + sBias[c0+1]);
            *(float2*)(orow0 + c0) = v0;
            *(float2*)(orow1 + c0) = v1;
        }
    }
}

// ---------------------------------------------------------------------------
// Flash attention with tf32 mma.sync. 128 threads (4 warps), 64 Q rows/block.
// Q fragments persist in registers. K tile [n][k] pad 132; V tile [k][n]
// pad 136; P tile [m][k] pad 68 (tf32 bits). P rows are warp-private.
// ---------------------------------------------------------------------------
__global__ __launch_bounds__(128) void attn_mma_kernel()
{
    extern __shared__ float sm[];
    float* Ks = sm;                    // 64*132 = 8448
    float* Vs = sm + 8448;             // 64*136 = 8704
    float* Ps = sm + 8448 + 8704;      // 64*68  = 4352   total 86016 B

    const int tid  = threadIdx.x;
    const int w    = tid >> 5;
    const int lane = tid & 31;
    const int quad = lane >> 2;
    const int qt   = lane & 3;
    const int qb   = blockIdx.x;       // 0..31
    const int bh   = blockIdx.y;       // 0..31
    const int b    = bh >> 3;
    const int h    = bh & 7;

    const float* Qg = g_q + (size_t)bh * SEQ * UNITS;
    const float* Kg = g_k + (size_t)bh * SEQ * UNITS;
    const float* Vg = g_v + (size_t)bh * SEQ * UNITS;

    const float qscale = 0.08838834764831845f;  // 1/sqrt(128)

    const int rl0 = w*16 + quad;       // block-local row 0..63
    const int rl1 = rl0 + 8;
    const int gr0 = qb*64 + rl0;       // global seq row
    const int gr1 = gr0 + 8;

    // Q fragments in registers, pre-scaled, tf32
    uint32_t qa[16][4];
    #pragma unroll
    for (int ks = 0; ks < 16; ks++) {
        int k = ks*8 + qt;
        qa[ks][0] = fbits(f2tf32(Qg[(size_t)gr0*128 + k    ] * qscale));
        qa[ks][1] = fbits(f2tf32(Qg[(size_t)gr1*128 + k    ] * qscale));
        qa[ks][2] = fbits(f2tf32(Qg[(size_t)gr0*128 + k + 4] * qscale));
        qa[ks][3] = fbits(f2tf32(Qg[(size_t)gr1*128 + k + 4] * qscale));
    }

    float m0 = -1e30f, m1 = -1e30f, l0 = 0.f, l1 = 0.f;
    float acc[16][4];
    #pragma unroll
    for (int nf = 0; nf < 16; nf++)
        #pragma unroll
        for (int e = 0; e < 4; e++) acc[nf][e] = 0.f;

    for (int kt = 0; kt < SEQ/64; kt++) {
        __syncthreads();   // everyone done with previous K/V tiles
        // load K tile 64x128 -> Ks[n][k] (tf32), V tile -> Vs[k][n] (tf32)
        const float* Kt = Kg + (size_t)kt*64*128;
        const float* Vt = Vg + (size_t)kt*64*128;
        #pragma unroll
        for (int i = 0; i < 16; i++) {
            int idx = i*128 + tid;       // 0..2047
            int row = idx >> 5;          // 0..63
            int c4  = idx & 31;          // 0..31
            float4 v = *(const float4*)(Kt + (size_t)row*128 + c4*4);
            v.x = f2tf32(v.x); v.y = f2tf32(v.y); v.z = f2tf32(v.z); v.w = f2tf32(v.w);
            *(float4*)(Ks + row*132 + c4*4) = v;
            float4 u = *(const float4*)(Vt + (size_t)row*128 + c4*4);
            u.x = f2tf32(u.x); u.y = f2tf32(u.y); u.z = f2tf32(u.z); u.w = f2tf32(u.w);
            *(float4*)(Vs + row*136 + c4*4) = u;
        }
        __syncthreads();

        // ---- scores: sc = Q(16x128) x K^T(64x128) per warp ----
        float sc[8][4];
        #pragma unroll
        for (int nf = 0; nf < 8; nf++)
            #pragma unroll
            for (int e = 0; e < 4; e++) sc[nf][e] = 0.f;

        #pragma unroll
        for (int ks = 0; ks < 16; ks++) {
            #pragma unroll
            for (int nf = 0; nf < 8; nf++) {
                int n = nf*8 + quad;
                uint32_t b0 = fbits(Ks[n*132 + ks*8 + qt]);
                uint32_t b1 = fbits(Ks[n*132 + ks*8 + 4 + qt]);
                mma8(sc[nf], qa[ks][0], qa[ks][1], qa[ks][2], qa[ks][3], b0, b1);
            }
        }

        // ---- online softmax ----
        float mt0 = -1e30f, mt1 = -1e30f;
        #pragma unroll
        for (int nf = 0; nf < 8; nf++) {
            mt0 = fmaxf(mt0, fmaxf(sc[nf][0], sc[nf][1]));
            mt1 = fmaxf(mt1, fmaxf(sc[nf][2], sc[nf][3]));
        }
        mt0 = fmaxf(mt0, __shfl_xor_sync(0xffffffffu, mt0, 1));
        mt0 = fmaxf(mt0, __shfl_xor_sync(0xffffffffu, mt0, 2));
        mt1 = fmaxf(mt1, __shfl_xor_sync(0xffffffffu, mt1, 1));
        mt1 = fmaxf(mt1, __shfl_xor_sync(0xffffffffu, mt1, 2));

        float mn0 = fmaxf(m0, mt0), mn1 = fmaxf(m1, mt1);
        float alpha0 = __expf(m0 - mn0), alpha1 = __expf(m1 - mn1);
        m0 = mn0; m1 = mn1;

        float rs0 = 0.f, rs1 = 0.f;
        #pragma unroll
        for (int nf = 0; nf < 8; nf++) {
            float p00 = __expf(sc[nf][0] - mn0);
            float p01 = __expf(sc[nf][1] - mn0);
            float p10 = __expf(sc[nf][2] - mn1);
            float p11 = __expf(sc[nf][3] - mn1);
            rs0 += p00 + p01;
            rs1 += p10 + p11;
            int col = nf*8 + qt*2;
            *(float2*)(Ps + rl0*68 + col) = make_float2(f2tf32(p00), f2tf32(p01));
            *(float2*)(Ps + rl1*68 + col) = make_float2(f2tf32(p10), f2tf32(p11));
        }
        rs0 += __shfl_xor_sync(0xffffffffu, rs0, 1);
        rs0 += __shfl_xor_sync(0xffffffffu, rs0, 2);
        rs1 += __shfl_xor_sync(0xffffffffu, rs1, 1);
        rs1 += __shfl_xor_sync(0xffffffffu, rs1, 2);
        l0 = l0*alpha0 + rs0;
        l1 = l1*alpha1 + rs1;

        #pragma unroll
        for (int nf = 0; nf < 16; nf++) {
            acc[nf][0] *= alpha0; acc[nf][1] *= alpha0;
            acc[nf][2] *= alpha1; acc[nf][3] *= alpha1;
        }
        __syncwarp();   // P rows are warp-private; make stores visible in-warp

        // ---- PV: acc += P(16x64) x V(64x128) per warp ----
        #pragma unroll
        for (int ks = 0; ks < 8; ks++) {
            uint32_t pa0 = fbits(Ps[(w*16 + quad    )*68 + ks*8 + qt    ]);
            uint32_t pa1 = fbits(Ps[(w*16 + quad + 8)*68 + ks*8 + qt    ]);
            uint32_t pa2 = fbits(Ps[(w*16 + quad    )*68 + ks*8 + 4 + qt]);
            uint32_t pa3 = fbits(Ps[(w*16 + quad + 8)*68 + ks*8 + 4 + qt]);
            #pragma unroll
            for (int nf = 0; nf < 16; nf++) {
                int n = nf*8 + quad;
                uint32_t b0 = fbits(Vs[(ks*8 + qt    )*136 + n]);
                uint32_t b1 = fbits(Vs[(ks*8 + 4 + qt)*136 + n]);
                mma8(acc[nf], pa0, pa1, pa2, pa3, b0, b1);
            }
        }
    }

    // ---- normalize + write flat [B, S, H*U] ----
    float inv0 = 1.0f / l0, inv1 = 1.0f / l1;
    float* o0 = g_flat + ((size_t)b*SEQ + gr0)*(HEADS*UNITS) + h*UNITS;
    float* o1 = g_flat + ((size_t)b*SEQ + gr1)*(HEADS*UNITS) + h*UNITS;
    #pragma unroll
    for (int nf = 0; nf < 16; nf++) {
        int col = nf*8 + qt*2;
        *(float2*)(o0 + col) = make_float2(acc[nf][0]*inv0, acc[nf][1]*inv0);
        *(float2*)(o1 + col) = make_float2(acc[nf][2]*inv1, acc[nf][3]*inv1);
    }
}

// ---------------------------------------------------------------------------
extern "C" void kernel_launch(void* const* d_in, const int* in_sizes, int n_in,
                              void* d_out, int out_size)
{
    (void)in_sizes; (void)n_in; (void)out_size;
    const float* x   = (const float*)d_in[0];
    const float* wq  = (const float*)d_in[1];
    const float* wk  = (const float*)d_in[2];
    const float* wv  = (const float*)d_in[3];
    const float* bq  = (const float*)d_in[4];
    const float* bk  = (const float*)d_in[5];
    const float* bv  = (const float*)d_in[6];
    const float* wh  = (const float*)d_in[7];
    const float* bh  = (const float*)d_in[8];
    float* out = (float*)d_out;

    const int gemm_smem = 4*128*36*4;         // 73728 B
    const int attn_smem = (8448+8704+4352)*4; // 86016 B
    cudaFuncSetAttribute(gemm_mma_kernel, cudaFuncAttributeMaxDynamicSharedMemorySize, gemm_smem);
    cudaFuncSetAttribute(attn_mma_kernel, cudaFuncAttributeMaxDynamicSharedMemorySize, attn_smem);

    transpose_w_kernel<<<dim3(32, 4, 25), dim3(32, 8)>>>(wq, wk, wv, wh);
    gemm_mma_kernel<<<dim3(64, 24), 256, gemm_smem>>>(x, 0, bq, bk, bv, bh, nullptr);
    attn_mma_kernel<<<dim3(SEQ/64, BATCH*HEADS), 128, attn_smem>>>();
    gemm_mma_kernel<<<dim3(64, 1), 256, gemm_smem>>>(nullptr, 1, bq, bk, bv, bh, out);
}

// round 5
// speedup vs baseline: 7.2217x; 2.8163x over previous
#include <cuda_runtime.h>
#include <cuda_fp16.h>
#include <cstdint>

#define BATCH 4
#define SEQ   2048
#define DIN   1024
#define HEADS 8
#define UNITS 128

// fp16 scratch (device globals: allocation inside kernel_launch is forbidden)
__device__ __half g_xh[(size_t)BATCH*SEQ*DIN];          // x converted to fp16
__device__ __half g_wth[(size_t)25*128*1024];           // transposed weights [n][k]
__device__ __half g_qh[(size_t)BATCH*HEADS*SEQ*UNITS];  // q (pre-scaled by 1/sqrt(128))
__device__ __half g_kh[(size_t)BATCH*HEADS*SEQ*UNITS];
__device__ __half g_vh[(size_t)BATCH*HEADS*SEQ*UNITS];
__device__ __half g_flath[(size_t)BATCH*SEQ*HEADS*UNITS];

// ---------------------------------------------------------------------------
// Helpers (sm_80-level PTX only: must compile for compute_103 virtual arch)
// ---------------------------------------------------------------------------
__device__ __forceinline__ uint32_t smem_u32(const void* p) {
    uint32_t a;
    asm("{ .reg .u64 t; cvta.to.shared.u64 t, %1; cvt.u32.u64 %0, t; }" : "=r"(a) : "l"(p));
    return a;
}
__device__ __forceinline__ void cp16(uint32_t dst, const void* src) {
    asm volatile("cp.async.cg.shared.global [%0], [%1], 16;"
                 :: "r"(dst), "l"(__cvta_generic_to_global(src)));
}
__device__ __forceinline__ void cp_commit() {
    asm volatile("cp.async.commit_group;");
}
template<int N> __device__ __forceinline__ void cp_wait() {
    asm volatile("cp.async.wait_group %0;" :: "n"(N));
}
__device__ __forceinline__ void ldm4(uint32_t& r0, uint32_t& r1, uint32_t& r2, uint32_t& r3,
                                     uint32_t addr) {
    asm volatile("ldmatrix.sync.aligned.m8n8.x4.shared.b16 {%0,%1,%2,%3}, [%4];"
                 : "=r"(r0), "=r"(r1), "=r"(r2), "=r"(r3) : "r"(addr));
}
__device__ __forceinline__ void ldm4t(uint32_t& r0, uint32_t& r1, uint32_t& r2, uint32_t& r3,
                                      uint32_t addr) {
    asm volatile("ldmatrix.sync.aligned.m8n8.x4.trans.shared.b16 {%0,%1,%2,%3}, [%4];"
                 : "=r"(r0), "=r"(r1), "=r"(r2), "=r"(r3) : "r"(addr));
}
__device__ __forceinline__ void mma16(float* c,
                                      uint32_t a0, uint32_t a1, uint32_t a2, uint32_t a3,
                                      uint32_t b0, uint32_t b1) {
    asm volatile(
        "mma.sync.aligned.m16n8k16.row.col.f32.f16.f16.f32 "
        "{%0,%1,%2,%3}, {%4,%5,%6,%7}, {%8,%9}, {%0,%1,%2,%3};"
        : "+f"(c[0]), "+f"(c[1]), "+f"(c[2]), "+f"(c[3])
        : "r"(a0), "r"(a1), "r"(a2), "r"(a3), "r"(b0), "r"(b1));
}
__device__ __forceinline__ uint32_t pack_h2(float a, float b) {
    __half2 h = __floats2half2_rn(a, b);
    return *reinterpret_cast<uint32_t*>(&h);
}

// ---------------------------------------------------------------------------
// x -> fp16
// ---------------------------------------------------------------------------
__global__ __launch_bounds__(256) void convert_x_kernel(const float* __restrict__ x) {
    size_t i = ((size_t)blockIdx.x * 256 + threadIdx.x) * 4;
    float4 v = *(const float4*)(x + i);
    *(__half2*)(g_xh + i)     = __floats2half2_rn(v.x, v.y);
    *(__half2*)(g_xh + i + 2) = __floats2half2_rn(v.z, v.w);
}

// ---------------------------------------------------------------------------
// Weight transpose + fp16: g_wth[g][n][k] = half(W_g[k][n])
// ---------------------------------------------------------------------------
__global__ __launch_bounds__(256) void transpose_w_kernel(
    const float* __restrict__ wq, const float* __restrict__ wk,
    const float* __restrict__ wv, const float* __restrict__ wh)
{
    __shared__ float t[32][33];
    const int g  = blockIdx.z;
    const int kb = blockIdx.x * 32;
    const int nb = blockIdx.y * 32;
    const int tx = threadIdx.x, ty = threadIdx.y;

    const float* W = (g < 8)  ? wq + (size_t)g * 131072
                   : (g < 16) ? wk + (size_t)(g - 8) * 131072
                   : (g < 24) ? wv + (size_t)(g - 16) * 131072
                              : wh;
    #pragma unroll
    for (int j = 0; j < 4; j++)
        t[ty + j*8][tx] = W[(size_t)(kb + ty + j*8) * 128 + nb + tx];
    __syncthreads();
    __half* outp = g_wth + (size_t)g * 131072;
    #pragma unroll
    for (int j = 0; j < 4; j++)
        outp[(size_t)(nb + ty + j*8) * 1024 + kb + tx] = __float2half(t[tx][ty + j*8]);
}

// ---------------------------------------------------------------------------
// fp16 mma GEMM: C[MTILE-row tile of M=8192, 128] = A[.,1024] x B^T + bias
// MF = m16 fragments per warp (MTILE = 32*MF). 8 warps = 2m x 4n.
// mode 0: A = g_xh, 24 GEMMs (blockIdx.y = proj*8+head) -> g_qh/g_kh/g_vh (half)
//         (q additionally scaled by 1/sqrt(128))
// mode 1: A = g_flath, B = g_wth[24] -> out1 (fp32)
// K chunks of 64, cp.async double-buffered. Smem rows padded to 9x16B.
// ---------------------------------------------------------------------------
template<int MF>
__global__ __launch_bounds__(256, 2) void gemm_h_kernel(
    int mode,
    const float* __restrict__ bq, const float* __restrict__ bk,
    const float* __restrict__ bv, const float* __restrict__ bhp,
    float* __restrict__ out1)
{
    constexpr int MTILE = 32 * MF;
    extern __shared__ char sm[];
    __shared__ float sBias[128];

    const uint32_t smb = smem_u32(sm);
    const int tid  = threadIdx.x;
    const int w    = tid >> 5;
    const int lane = tid & 31;
    const int quad = lane >> 2;
    const int qt   = lane & 3;
    const int wm   = w >> 2;          // 0..1
    const int wn   = w & 3;           // 0..3
    const int mtile = blockIdx.x;
    const int g     = blockIdx.y;
    const int proj  = g >> 3;
    const int head  = g & 7;

    const __half* A = (mode == 0) ? g_xh : g_flath;
    const __half* B = g_wth + (size_t)((mode == 0) ? g : 24) * 131072;
    const float* bias = (mode == 0)
        ? ((proj == 0 ? bq : proj == 1 ? bk : bv) + head * 128)
        : bhp;
    if (tid < 128) sBias[tid] = bias[tid];

    const __half* Abase = A + (size_t)mtile * MTILE * 1024;

    // smem layout (bytes): buf b: A tile at b*(MTILE+128)*144, B tile after A.
    const uint32_t bufSize = (MTILE + 128) * 144;

    auto issue = [&](int c, int buf) {
        const int k0 = c * 64;
        uint32_t ab = smb + buf * bufSize;
        uint32_t bb = ab + MTILE * 144;
        #pragma unroll
        for (int t = 0; t < MF; t++) {         // MTILE*8 ops, 256 threads
            int i = tid + t * 256;
            int row = i >> 3, cu = i & 7;
            cp16(ab + (row * 9 + cu) * 16, Abase + (size_t)row * 1024 + k0 + cu * 8);
        }
        #pragma unroll
        for (int t = 0; t < 4; t++) {          // 128*8 ops
            int i = tid + t * 256;
            int row = i >> 3, cu = i & 7;
            cp16(bb + (row * 9 + cu) * 16, B + (size_t)row * 1024 + k0 + cu * 8);
        }
        cp_commit();
    };

    float acc[MF][4][4];
    #pragma unroll
    for (int i = 0; i < MF; i++)
        #pragma unroll
        for (int j = 0; j < 4; j++)
            #pragma unroll
            for (int e = 0; e < 4; e++) acc[i][j][e] = 0.f;

    const int lrow  = (lane & 7) + (lane & 8);  // = lane % 16
    const int lunit = lane >> 4;                // 0 or 1

    issue(0, 0);
    const int NCH = 16;
    for (int c = 0; c < NCH; c++) {
        if (c + 1 < NCH) issue(c + 1, (c + 1) & 1);
        if (c + 1 < NCH) cp_wait<1>(); else cp_wait<0>();
        __syncthreads();

        uint32_t ab = smb + (c & 1) * bufSize;
        uint32_t bb = ab + MTILE * 144;

        #pragma unroll
        for (int ks = 0; ks < 4; ks++) {
            uint32_t af[MF][4];
            #pragma unroll
            for (int mf = 0; mf < MF; mf++) {
                int r0 = wm * (MF * 16) + mf * 16;
                ldm4(af[mf][0], af[mf][1], af[mf][2], af[mf][3],
                     ab + ((r0 + lrow) * 9 + 2 * ks + lunit) * 16);
            }
            #pragma unroll
            for (int nf2 = 0; nf2 < 2; nf2++) {
                int n0 = wn * 32 + nf2 * 16;
                uint32_t b0A, b0B, b1A, b1B;
                ldm4(b0A, b0B, b1A, b1B,
                     bb + ((n0 + lrow) * 9 + 2 * ks + lunit) * 16);
                #pragma unroll
                for (int mf = 0; mf < MF; mf++) {
                    mma16(acc[mf][nf2*2],   af[mf][0], af[mf][1], af[mf][2], af[mf][3], b0A, b1A);
                    mma16(acc[mf][nf2*2+1], af[mf][0], af[mf][1], af[mf][2], af[mf][3], b0B, b1B);
                }
            }
        }
        __syncthreads();
    }

    // epilogue
    const float scale = (mode == 0 && proj == 0) ? 0.08838834764831845f : 1.0f;
    #pragma unroll
    for (int mf = 0; mf < MF; mf++) {
        int rl0 = wm * (MF * 16) + mf * 16 + quad;
        int R0  = mtile * MTILE + rl0;
        int R1  = R0 + 8;
        if (mode == 0) {
            __half* ob = (proj == 0) ? g_qh : (proj == 1) ? g_kh : g_vh;
            int b0i = R0 >> 11, s0 = R0 & 2047;
            int b1i = R1 >> 11, s1 = R1 & 2047;
            __half* o0 = ob + (((size_t)(b0i*8 + head))*2048 + s0)*128;
            __half* o1 = ob + (((size_t)(b1i*8 + head))*2048 + s1)*128;
            #pragma unroll
            for (int nf = 0; nf < 4; nf++) {
                int c0 = wn*32 + nf*8 + qt*2;
                *(uint32_t*)(o0 + c0) = pack_h2((acc[mf][nf][0] + sBias[c0]) * scale,
                                                (acc[mf][nf][1] + sBias[c0+1]) * scale);
                *(uint32_t*)(o1 + c0) = pack_h2((acc[mf][nf][2] + sBias[c0]) * scale,
                                                (acc[mf][nf][3] + sBias[c0+1]) * scale);
            }
        } else {
            float* o0 = out1 + (size_t)R0 * 128;
            float* o1 = out1 + (size_t)R1 * 128;
            #pragma unroll
            for (int nf = 0; nf < 4; nf++) {
                int c0 = wn*32 + nf*8 + qt*2;
                *(float2*)(o0 + c0) = make_float2(acc[mf][nf][0] + sBias[c0],
                                                  acc[mf][nf][1] + sBias[c0+1]);
                *(float2*)(o1 + c0) = make_float2(acc[mf][nf][2] + sBias[c0],
                                                  acc[mf][nf][3] + sBias[c0+1]);
            }
        }
    }
}

// ---------------------------------------------------------------------------
// Flash attention, fp16 mma. 256 threads (8 warps), 128 Q rows/block,
// K/V tiles of 64 keys, cp.async double-buffered.
// Q fragments persist in registers; P stays in registers (score C-frags
// repacked as PV A-frags). Smem rows padded to 17x16B (conflict-free ldmatrix).
// ---------------------------------------------------------------------------
__global__ __launch_bounds__(256) void attn_h_kernel()
{
    extern __shared__ char sm[];
    const uint32_t smb = smem_u32(sm);
    // K bufs at 0, 17408; V bufs at 34816, 34816+17408. total 69632 B.

    const int tid  = threadIdx.x;
    const int w    = tid >> 5;
    const int lane = tid & 31;
    const int quad = lane >> 2;
    const int qt   = lane & 3;
    const int qb   = blockIdx.x;      // 0..15
    const int bh   = blockIdx.y;      // 0..31
    const int b    = bh >> 3;
    const int h    = bh & 7;

    const __half* Qg = g_qh + ((size_t)bh * SEQ + qb * 128) * 128;
    const __half* Kg = g_kh + (size_t)bh * SEQ * 128;
    const __half* Vg = g_vh + (size_t)bh * SEQ * 128;

    const int lrow  = (lane & 7) + (lane & 8);
    const int lunit = lane >> 4;

    // Q fragments from global (q already scaled by 1/sqrt(128))
    uint32_t qa[8][4];
    {
        const __half* q0 = Qg + (size_t)(w*16 + quad) * 128 + qt*2;
        #pragma unroll
        for (int ks = 0; ks < 8; ks++) {
            qa[ks][0] = *(const uint32_t*)(q0 + ks*16);
            qa[ks][1] = *(const uint32_t*)(q0 + ks*16 + 8*128);
            qa[ks][2] = *(const uint32_t*)(q0 + ks*16 + 8);
            qa[ks][3] = *(const uint32_t*)(q0 + ks*16 + 8*128 + 8);
        }
    }

    auto issue = [&](int kt, int buf) {
        const __half* Kt = Kg + (size_t)kt * 64 * 128;
        const __half* Vt = Vg + (size_t)kt * 64 * 128;
        uint32_t kb = smb + buf * 17408;
        uint32_t vb = smb + 34816 + buf * 17408;
        #pragma unroll
        for (int t = 0; t < 4; t++) {
            int i = tid + t * 256;
            int row = i >> 4, cu = i & 15;
            cp16(kb + (row*17 + cu)*16, Kt + (size_t)row*128 + cu*8);
        }
        #pragma unroll
        for (int t = 0; t < 4; t++) {
            int i = tid + t * 256;
            int row = i >> 4, cu = i & 15;
            cp16(vb + (row*17 + cu)*16, Vt + (size_t)row*128 + cu*8);
        }
        cp_commit();
    };

    float m0 = -1e30f, m1 = -1e30f, l0 = 0.f, l1 = 0.f;
    float acc[16][4];
    #pragma unroll
    for (int nt = 0; nt < 16; nt++)
        #pragma unroll
        for (int e = 0; e < 4; e++) acc[nt][e] = 0.f;

    issue(0, 0);
    const int NT = SEQ / 64;
    for (int kt = 0; kt < NT; kt++) {
        if (kt + 1 < NT) issue(kt + 1, (kt + 1) & 1);
        if (kt + 1 < NT) cp_wait<1>(); else cp_wait<0>();
        __syncthreads();

        uint32_t kbase = smb + (kt & 1) * 17408;
        uint32_t vbase = smb + 34816 + (kt & 1) * 17408;

        // ---- scores: 16 q-rows x 64 keys per warp ----
        float sc[8][4];
        #pragma unroll
        for (int nt = 0; nt < 8; nt++)
            #pragma unroll
            for (int e = 0; e < 4; e++) sc[nt][e] = 0.f;

        #pragma unroll
        for (int ks = 0; ks < 8; ks++) {
            #pragma unroll
            for (int nf2 = 0; nf2 < 4; nf2++) {
                uint32_t b0A, b0B, b1A, b1B;
                ldm4(b0A, b0B, b1A, b1B,
                     kbase + ((nf2*16 + lrow)*17 + 2*ks + lunit)*16);
                mma16(sc[nf2*2],   qa[ks][0], qa[ks][1], qa[ks][2], qa[ks][3], b0A, b1A);
                mma16(sc[nf2*2+1], qa[ks][0], qa[ks][1], qa[ks][2], qa[ks][3], b0B, b1B);
            }
        }

        // ---- online softmax (rows quad / quad+8; reduce over qt lanes) ----
        float mt0 = -1e30f, mt1 = -1e30f;
        #pragma unroll
        for (int nt = 0; nt < 8; nt++) {
            mt0 = fmaxf(mt0, fmaxf(sc[nt][0], sc[nt][1]));
            mt1 = fmaxf(mt1, fmaxf(sc[nt][2], sc[nt][3]));
        }
        mt0 = fmaxf(mt0, __shfl_xor_sync(0xffffffffu, mt0, 1));
        mt0 = fmaxf(mt0, __shfl_xor_sync(0xffffffffu, mt0, 2));
        mt1 = fmaxf(mt1, __shfl_xor_sync(0xffffffffu, mt1, 1));
        mt1 = fmaxf(mt1, __shfl_xor_sync(0xffffffffu, mt1, 2));

        float mn0 = fmaxf(m0, mt0), mn1 = fmaxf(m1, mt1);
        float alpha0 = __expf(m0 - mn0), alpha1 = __expf(m1 - mn1);
        m0 = mn0; m1 = mn1;

        uint32_t ph[8][2];
        float rs0 = 0.f, rs1 = 0.f;
        #pragma unroll
        for (int nt = 0; nt < 8; nt++) {
            float p00 = __expf(sc[nt][0] - mn0);
            float p01 = __expf(sc[nt][1] - mn0);
            float p10 = __expf(sc[nt][2] - mn1);
            float p11 = __expf(sc[nt][3] - mn1);
            rs0 += p00 + p01;
            rs1 += p10 + p11;
            ph[nt][0] = pack_h2(p00, p01);
            ph[nt][1] = pack_h2(p10, p11);
        }
        rs0 += __shfl_xor_sync(0xffffffffu, rs0, 1);
        rs0 += __shfl_xor_sync(0xffffffffu, rs0, 2);
        rs1 += __shfl_xor_sync(0xffffffffu, rs1, 1);
        rs1 += __shfl_xor_sync(0xffffffffu, rs1, 2);
        l0 = l0*alpha0 + rs0;
        l1 = l1*alpha1 + rs1;

        #pragma unroll
        for (int nt = 0; nt < 16; nt++) {
            acc[nt][0] *= alpha0; acc[nt][1] *= alpha0;
            acc[nt][2] *= alpha1; acc[nt][3] *= alpha1;
        }

        // ---- PV: acc += P(16x64) x V(64x128); V^T frags via ldmatrix.trans ----
        #pragma unroll
        for (int kks = 0; kks < 4; kks++) {
            uint32_t a0 = ph[kks*2][0],   a1 = ph[kks*2][1];
            uint32_t a2 = ph[kks*2+1][0], a3 = ph[kks*2+1][1];
            #pragma unroll
            for (int df2 = 0; df2 < 8; df2++) {
                uint32_t b0A, b1A, b0B, b1B;
                ldm4t(b0A, b1A, b0B, b1B,
                      vbase + ((kks*16 + lrow)*17 + 2*df2 + lunit)*16);
                mma16(acc[df2*2],   a0, a1, a2, a3, b0A, b1A);
                mma16(acc[df2*2+1], a0, a1, a2, a3, b0B, b1B);
            }
        }
        __syncthreads();   // all warps done with this buffer before reuse
    }

    // ---- normalize + write flat [B, S, H*U] as fp16 ----
    float inv0 = 1.0f / l0, inv1 = 1.0f / l1;
    int s0 = qb*128 + w*16 + quad;
    int s1 = s0 + 8;
    __half* o0 = g_flath + ((size_t)b*SEQ + s0)*(HEADS*UNITS) + h*UNITS;
    __half* o1 = g_flath + ((size_t)b*SEQ + s1)*(HEADS*UNITS) + h*UNITS;
    #pragma unroll
    for (int nt = 0; nt < 16; nt++) {
        int c0 = nt*8 + qt*2;
        *(uint32_t*)(o0 + c0) = pack_h2(acc[nt][0]*inv0, acc[nt][1]*inv0);
        *(uint32_t*)(o1 + c0) = pack_h2(acc[nt][2]*inv1, acc[nt][3]*inv1);
    }
}

// ---------------------------------------------------------------------------
extern "C" void kernel_launch(void* const* d_in, const int* in_sizes, int n_in,
                              void* d_out, int out_size)
{
    (void)in_sizes; (void)n_in; (void)out_size;
    const float* x   = (const float*)d_in[0];
    const float* wq  = (const float*)d_in[1];
    const float* wk  = (const float*)d_in[2];
    const float* wv  = (const float*)d_in[3];
    const float* bq  = (const float*)d_in[4];
    const float* bk  = (const float*)d_in[5];
    const float* bv  = (const float*)d_in[6];
    const float* wh  = (const float*)d_in[7];
    const float* bh  = (const float*)d_in[8];
    float* out = (float*)d_out;

    const int gemm4_smem = 2 * (128 + 128) * 144;   // 73728
    const int gemm2_smem = 2 * (64 + 128) * 144;    // 55296
    const int attn_smem  = 4 * 17408;               // 69632
    cudaFuncSetAttribute(gemm_h_kernel<4>, cudaFuncAttributeMaxDynamicSharedMemorySize, gemm4_smem);
    cudaFuncSetAttribute(gemm_h_kernel<2>, cudaFuncAttributeMaxDynamicSharedMemorySize, gemm2_smem);
    cudaFuncSetAttribute(attn_h_kernel,    cudaFuncAttributeMaxDynamicSharedMemorySize, attn_smem);

    convert_x_kernel<<<(BATCH*SEQ*DIN)/(256*4), 256>>>(x);
    transpose_w_kernel<<<dim3(32, 4, 25), dim3(32, 8)>>>(wq, wk, wv, wh);
    gemm_h_kernel<4><<<dim3(64, 24), 256, gemm4_smem>>>(0, bq, bk, bv, bh, nullptr);
    attn_h_kernel<<<dim3(16, 32), 256, attn_smem>>>();
    gemm_h_kernel<2><<<dim3(128, 1), 256, gemm2_smem>>>(1, bq, bk, bv, bh, out);
}

// round 6
// speedup vs baseline: 7.5793x; 1.0495x over previous
#include <cuda_runtime.h>
#include <cuda_fp16.h>
#include <cstdint>

#define BATCH 4
#define SEQ   2048
#define DIN   1024
#define HEADS 8
#define UNITS 128

// fp16 scratch (device globals: allocation inside kernel_launch is forbidden)
__device__ __half g_xh[(size_t)BATCH*SEQ*DIN];          // x converted to fp16
__device__ __half g_wth[(size_t)25*128*1024];           // transposed weights [n][k]
__device__ __half g_qh[(size_t)BATCH*HEADS*SEQ*UNITS];  // q (pre-scaled by log2e/sqrt(128))
__device__ __half g_kh[(size_t)BATCH*HEADS*SEQ*UNITS];
__device__ __half g_vh[(size_t)BATCH*HEADS*SEQ*UNITS];
__device__ __half g_flath[(size_t)BATCH*SEQ*HEADS*UNITS];

// ---------------------------------------------------------------------------
// Helpers (sm_80-level PTX only: must compile for compute_103 virtual arch)
// ---------------------------------------------------------------------------
__device__ __forceinline__ uint32_t smem_u32(const void* p) {
    uint32_t a;
    asm("{ .reg .u64 t; cvta.to.shared.u64 t, %1; cvt.u32.u64 %0, t; }" : "=r"(a) : "l"(p));
    return a;
}
__device__ __forceinline__ void cp16(uint32_t dst, const void* src) {
    asm volatile("cp.async.cg.shared.global [%0], [%1], 16;"
                 :: "r"(dst), "l"(__cvta_generic_to_global(src)));
}
__device__ __forceinline__ void cp_commit() {
    asm volatile("cp.async.commit_group;");
}
template<int N> __device__ __forceinline__ void cp_wait() {
    asm volatile("cp.async.wait_group %0;" :: "n"(N));
}
__device__ __forceinline__ void bar_sync(int id) {
    asm volatile("bar.sync %0, 128;" :: "r"(id) : "memory");
}
__device__ __forceinline__ void ldm4(uint32_t& r0, uint32_t& r1, uint32_t& r2, uint32_t& r3,
                                     uint32_t addr) {
    asm volatile("ldmatrix.sync.aligned.m8n8.x4.shared.b16 {%0,%1,%2,%3}, [%4];"
                 : "=r"(r0), "=r"(r1), "=r"(r2), "=r"(r3) : "r"(addr));
}
__device__ __forceinline__ void ldm4t(uint32_t& r0, uint32_t& r1, uint32_t& r2, uint32_t& r3,
                                      uint32_t addr) {
    asm volatile("ldmatrix.sync.aligned.m8n8.x4.trans.shared.b16 {%0,%1,%2,%3}, [%4];"
                 : "=r"(r0), "=r"(r1), "=r"(r2), "=r"(r3) : "r"(addr));
}
__device__ __forceinline__ void mma16(float* c,
                                      uint32_t a0, uint32_t a1, uint32_t a2, uint32_t a3,
                                      uint32_t b0, uint32_t b1) {
    asm volatile(
        "mma.sync.aligned.m16n8k16.row.col.f32.f16.f16.f32 "
        "{%0,%1,%2,%3}, {%4,%5,%6,%7}, {%8,%9}, {%0,%1,%2,%3};"
        : "+f"(c[0]), "+f"(c[1]), "+f"(c[2]), "+f"(c[3])
        : "r"(a0), "r"(a1), "r"(a2), "r"(a3), "r"(b0), "r"(b1));
}
__device__ __forceinline__ uint32_t pack_h2(float a, float b) {
    __half2 h = __floats2half2_rn(a, b);
    return *reinterpret_cast<uint32_t*>(&h);
}

// ---------------------------------------------------------------------------
// x -> fp16
// ---------------------------------------------------------------------------
__global__ __launch_bounds__(256) void convert_x_kernel(const float* __restrict__ x) {
    size_t i = ((size_t)blockIdx.x * 256 + threadIdx.x) * 4;
    float4 v = *(const float4*)(x + i);
    *(__half2*)(g_xh + i)     = __floats2half2_rn(v.x, v.y);
    *(__half2*)(g_xh + i + 2) = __floats2half2_rn(v.z, v.w);
}

// ---------------------------------------------------------------------------
// Weight transpose + fp16: g_wth[g][n][k] = half(W_g[k][n])
// ---------------------------------------------------------------------------
__global__ __launch_bounds__(256) void transpose_w_kernel(
    const float* __restrict__ wq, const float* __restrict__ wk,
    const float* __restrict__ wv, const float* __restrict__ wh)
{
    __shared__ float t[32][33];
    const int g  = blockIdx.z;
    const int kb = blockIdx.x * 32;
    const int nb = blockIdx.y * 32;
    const int tx = threadIdx.x, ty = threadIdx.y;

    const float* W = (g < 8)  ? wq + (size_t)g * 131072
                   : (g < 16) ? wk + (size_t)(g - 8) * 131072
                   : (g < 24) ? wv + (size_t)(g - 16) * 131072
                              : wh;
    #pragma unroll
    for (int j = 0; j < 4; j++)
        t[ty + j*8][tx] = W[(size_t)(kb + ty + j*8) * 128 + nb + tx];
    __syncthreads();
    __half* outp = g_wth + (size_t)g * 131072;
    #pragma unroll
    for (int j = 0; j < 4; j++)
        outp[(size_t)(nb + ty + j*8) * 1024 + kb + tx] = __float2half(t[tx][ty + j*8]);
}

// ---------------------------------------------------------------------------
// fp16 mma GEMM (unchanged from R5 except q scale now includes log2e)
// ---------------------------------------------------------------------------
template<int MF>
__global__ __launch_bounds__(256, 2) void gemm_h_kernel(
    int mode,
    const float* __restrict__ bq, const float* __restrict__ bk,
    const float* __restrict__ bv, const float* __restrict__ bhp,
    float* __restrict__ out1)
{
    constexpr int MTILE = 32 * MF;
    extern __shared__ char sm[];
    __shared__ float sBias[128];

    const uint32_t smb = smem_u32(sm);
    const int tid  = threadIdx.x;
    const int w    = tid >> 5;
    const int lane = tid & 31;
    const int quad = lane >> 2;
    const int qt   = lane & 3;
    const int wm   = w >> 2;
    const int wn   = w & 3;
    const int mtile = blockIdx.x;
    const int g     = blockIdx.y;
    const int proj  = g >> 3;
    const int head  = g & 7;

    const __half* A = (mode == 0) ? g_xh : g_flath;
    const __half* B = g_wth + (size_t)((mode == 0) ? g : 24) * 131072;
    const float* bias = (mode == 0)
        ? ((proj == 0 ? bq : proj == 1 ? bk : bv) + head * 128)
        : bhp;
    if (tid < 128) sBias[tid] = bias[tid];

    const __half* Abase = A + (size_t)mtile * MTILE * 1024;
    const uint32_t bufSize = (MTILE + 128) * 144;

    auto issue = [&](int c, int buf) {
        const int k0 = c * 64;
        uint32_t ab = smb + buf * bufSize;
        uint32_t bb = ab + MTILE * 144;
        #pragma unroll
        for (int t = 0; t < MF; t++) {
            int i = tid + t * 256;
            int row = i >> 3, cu = i & 7;
            cp16(ab + (row * 9 + cu) * 16, Abase + (size_t)row * 1024 + k0 + cu * 8);
        }
        #pragma unroll
        for (int t = 0; t < 4; t++) {
            int i = tid + t * 256;
            int row = i >> 3, cu = i & 7;
            cp16(bb + (row * 9 + cu) * 16, B + (size_t)row * 1024 + k0 + cu * 8);
        }
        cp_commit();
    };

    float acc[MF][4][4];
    #pragma unroll
    for (int i = 0; i < MF; i++)
        #pragma unroll
        for (int j = 0; j < 4; j++)
            #pragma unroll
            for (int e = 0; e < 4; e++) acc[i][j][e] = 0.f;

    const int lrow  = (lane & 7) + (lane & 8);
    const int lunit = lane >> 4;

    issue(0, 0);
    const int NCH = 16;
    for (int c = 0; c < NCH; c++) {
        if (c + 1 < NCH) issue(c + 1, (c + 1) & 1);
        if (c + 1 < NCH) cp_wait<1>(); else cp_wait<0>();
        __syncthreads();

        uint32_t ab = smb + (c & 1) * bufSize;
        uint32_t bb = ab + MTILE * 144;

        #pragma unroll
        for (int ks = 0; ks < 4; ks++) {
            uint32_t af[MF][4];
            #pragma unroll
            for (int mf = 0; mf < MF; mf++) {
                int r0 = wm * (MF * 16) + mf * 16;
                ldm4(af[mf][0], af[mf][1], af[mf][2], af[mf][3],
                     ab + ((r0 + lrow) * 9 + 2 * ks + lunit) * 16);
            }
            #pragma unroll
            for (int nf2 = 0; nf2 < 2; nf2++) {
                int n0 = wn * 32 + nf2 * 16;
                uint32_t b0A, b0B, b1A, b1B;
                ldm4(b0A, b0B, b1A, b1B,
                     bb + ((n0 + lrow) * 9 + 2 * ks + lunit) * 16);
                #pragma unroll
                for (int mf = 0; mf < MF; mf++) {
                    mma16(acc[mf][nf2*2],   af[mf][0], af[mf][1], af[mf][2], af[mf][3], b0A, b1A);
                    mma16(acc[mf][nf2*2+1], af[mf][0], af[mf][1], af[mf][2], af[mf][3], b0B, b1B);
                }
            }
        }
        __syncthreads();
    }

    // q gets log2e/sqrt(128) so attention can run softmax in exp2 domain
    const float scale = (mode == 0 && proj == 0)
                      ? (1.4426950408889634f * 0.08838834764831845f) : 1.0f;
    #pragma unroll
    for (int mf = 0; mf < MF; mf++) {
        int rl0 = wm * (MF * 16) + mf * 16 + quad;
        int R0  = mtile * MTILE + rl0;
        int R1  = R0 + 8;
        if (mode == 0) {
            __half* ob = (proj == 0) ? g_qh : (proj == 1) ? g_kh : g_vh;
            int b0i = R0 >> 11, s0 = R0 & 2047;
            int b1i = R1 >> 11, s1 = R1 & 2047;
            __half* o0 = ob + (((size_t)(b0i*8 + head))*2048 + s0)*128;
            __half* o1 = ob + (((size_t)(b1i*8 + head))*2048 + s1)*128;
            #pragma unroll
            for (int nf = 0; nf < 4; nf++) {
                int c0 = wn*32 + nf*8 + qt*2;
                *(uint32_t*)(o0 + c0) = pack_h2((acc[mf][nf][0] + sBias[c0]) * scale,
                                                (acc[mf][nf][1] + sBias[c0+1]) * scale);
                *(uint32_t*)(o1 + c0) = pack_h2((acc[mf][nf][2] + sBias[c0]) * scale,
                                                (acc[mf][nf][3] + sBias[c0+1]) * scale);
            }
        } else {
            float* o0 = out1 + (size_t)R0 * 128;
            float* o1 = out1 + (size_t)R1 * 128;
            #pragma unroll
            for (int nf = 0; nf < 4; nf++) {
                int c0 = wn*32 + nf*8 + qt*2;
                *(float2*)(o0 + c0) = make_float2(acc[mf][nf][0] + sBias[c0],
                                                  acc[mf][nf][1] + sBias[c0+1]);
                *(float2*)(o1 + c0) = make_float2(acc[mf][nf][2] + sBias[c0],
                                                  acc[mf][nf][3] + sBias[c0+1]);
            }
        }
    }
}

// ---------------------------------------------------------------------------
// Flash attention, split-K across two warp groups.
// CTA: 64 Q rows, 8 warps. Group A (w0-3): keys 0..1023, group B (w4-7):
// keys 1024..2047. Each group: own double-buffered K/V ring, own named
// barrier -> groups drift out of phase, overlapping softmax with HMMA.
// Softmax in exp2 domain (log2e pre-folded into q). Final merge via smem.
// ---------------------------------------------------------------------------
__global__ __launch_bounds__(256) void attn_h_kernel()
{
    extern __shared__ char sm[];
    const uint32_t smb = smem_u32(sm);
    // per group: 2 stages x (K 17408 + V 17408) = 69632 B; group B at +69632.
    // merge area (reuses group A ring after loop): macc 64x132 f32 @0,
    // marr @33792, larr @34048.

    const int tid  = threadIdx.x;
    const int w    = tid >> 5;
    const int wg   = w >> 2;          // 0 = group A, 1 = group B
    const int wl   = w & 3;           // warp within group
    const int gtid = tid & 127;       // thread within group
    const int lane = tid & 31;
    const int quad = lane >> 2;
    const int qt   = lane & 3;
    const int qb   = blockIdx.x;      // 0..31 (64-row q tile)
    const int bh   = blockIdx.y;      // 0..31
    const int b    = bh >> 3;
    const int h    = bh & 7;

    const __half* Qg = g_qh + ((size_t)bh * SEQ + qb * 64) * 128;
    const __half* Kg = g_kh + ((size_t)bh * SEQ + wg * 1024) * 128;
    const __half* Vg = g_vh + ((size_t)bh * SEQ + wg * 1024) * 128;

    const int lrow  = (lane & 7) + (lane & 8);
    const int lunit = lane >> 4;
    const uint32_t gbase = smb + wg * 69632;

    // Q fragments (q pre-scaled by log2e/sqrt(128) in projection)
    uint32_t qa[8][4];
    {
        const __half* q0 = Qg + (size_t)(wl*16 + quad) * 128 + qt*2;
        #pragma unroll
        for (int ks = 0; ks < 8; ks++) {
            qa[ks][0] = *(const uint32_t*)(q0 + ks*16);
            qa[ks][1] = *(const uint32_t*)(q0 + ks*16 + 8*128);
            qa[ks][2] = *(const uint32_t*)(q0 + ks*16 + 8);
            qa[ks][3] = *(const uint32_t*)(q0 + ks*16 + 8*128 + 8);
        }
    }

    auto issue = [&](int kt, int buf) {
        const __half* Kt = Kg + (size_t)kt * 64 * 128;
        const __half* Vt = Vg + (size_t)kt * 64 * 128;
        uint32_t kb = gbase + buf * 34816;
        uint32_t vb = kb + 17408;
        #pragma unroll
        for (int t = 0; t < 8; t++) {
            int i = gtid + t * 128;
            int row = i >> 4, cu = i & 15;
            cp16(kb + (row*17 + cu)*16, Kt + (size_t)row*128 + cu*8);
        }
        #pragma unroll
        for (int t = 0; t < 8; t++) {
            int i = gtid + t * 128;
            int row = i >> 4, cu = i & 15;
            cp16(vb + (row*17 + cu)*16, Vt + (size_t)row*128 + cu*8);
        }
        cp_commit();
    };

    float m0 = -1e30f, m1 = -1e30f, l0 = 0.f, l1 = 0.f;
    float acc[16][4];
    #pragma unroll
    for (int nt = 0; nt < 16; nt++)
        #pragma unroll
        for (int e = 0; e < 4; e++) acc[nt][e] = 0.f;

    issue(0, 0);
    const int NT = 16;  // 1024 keys per group / 64
    for (int kt = 0; kt < NT; kt++) {
        if (kt + 1 < NT) {
            bar_sync(1 + wg);        // group done with buffer (kt+1)&1 (read at kt-1)
            issue(kt + 1, (kt + 1) & 1);
            cp_wait<1>();            // tile kt landed
        } else {
            cp_wait<0>();
        }
        bar_sync(1 + wg);            // tile kt visible to whole group

        uint32_t kbase = gbase + (kt & 1) * 34816;
        uint32_t vbase = kbase + 17408;

        // ---- scores: 16 q-rows x 64 keys per warp ----
        float sc[8][4];
        #pragma unroll
        for (int nt = 0; nt < 8; nt++)
            #pragma unroll
            for (int e = 0; e < 4; e++) sc[nt][e] = 0.f;

        #pragma unroll
        for (int ks = 0; ks < 8; ks++) {
            #pragma unroll
            for (int nf2 = 0; nf2 < 4; nf2++) {
                uint32_t b0A, b0B, b1A, b1B;
                ldm4(b0A, b0B, b1A, b1B,
                     kbase + ((nf2*16 + lrow)*17 + 2*ks + lunit)*16);
                mma16(sc[nf2*2],   qa[ks][0], qa[ks][1], qa[ks][2], qa[ks][3], b0A, b1A);
                mma16(sc[nf2*2+1], qa[ks][0], qa[ks][1], qa[ks][2], qa[ks][3], b0B, b1B);
            }
        }

        // ---- online softmax in exp2 domain ----
        float mt0 = -1e30f, mt1 = -1e30f;
        #pragma unroll
        for (int nt = 0; nt < 8; nt++) {
            mt0 = fmaxf(mt0, fmaxf(sc[nt][0], sc[nt][1]));
            mt1 = fmaxf(mt1, fmaxf(sc[nt][2], sc[nt][3]));
        }
        mt0 = fmaxf(mt0, __shfl_xor_sync(0xffffffffu, mt0, 1));
        mt0 = fmaxf(mt0, __shfl_xor_sync(0xffffffffu, mt0, 2));
        mt1 = fmaxf(mt1, __shfl_xor_sync(0xffffffffu, mt1, 1));
        mt1 = fmaxf(mt1, __shfl_xor_sync(0xffffffffu, mt1, 2));

        float mn0 = fmaxf(m0, mt0), mn1 = fmaxf(m1, mt1);
        float alpha0 = exp2f(m0 - mn0), alpha1 = exp2f(m1 - mn1);
        m0 = mn0; m1 = mn1;

        uint32_t ph[8][2];
        float rs0 = 0.f, rs1 = 0.f;
        #pragma unroll
        for (int nt = 0; nt < 8; nt++) {
            float p00 = exp2f(sc[nt][0] - mn0);
            float p01 = exp2f(sc[nt][1] - mn0);
            float p10 = exp2f(sc[nt][2] - mn1);
            float p11 = exp2f(sc[nt][3] - mn1);
            rs0 += p00 + p01;
            rs1 += p10 + p11;
            ph[nt][0] = pack_h2(p00, p01);
            ph[nt][1] = pack_h2(p10, p11);
        }
        rs0 += __shfl_xor_sync(0xffffffffu, rs0, 1);
        rs0 += __shfl_xor_sync(0xffffffffu, rs0, 2);
        rs1 += __shfl_xor_sync(0xffffffffu, rs1, 1);
        rs1 += __shfl_xor_sync(0xffffffffu, rs1, 2);
        l0 = l0*alpha0 + rs0;
        l1 = l1*alpha1 + rs1;

        #pragma unroll
        for (int nt = 0; nt < 16; nt++) {
            acc[nt][0] *= alpha0; acc[nt][1] *= alpha0;
            acc[nt][2] *= alpha1; acc[nt][3] *= alpha1;
        }

        // ---- PV: acc += P(16x64) x V(64x128) ----
        #pragma unroll
        for (int kks = 0; kks < 4; kks++) {
            uint32_t a0 = ph[kks*2][0],   a1 = ph[kks*2][1];
            uint32_t a2 = ph[kks*2+1][0], a3 = ph[kks*2+1][1];
            #pragma unroll
            for (int df2 = 0; df2 < 8; df2++) {
                uint32_t b0A, b1A, b0B, b1B;
                ldm4t(b0A, b1A, b0B, b1B,
                      vbase + ((kks*16 + lrow)*17 + 2*df2 + lunit)*16);
                mma16(acc[df2*2],   a0, a1, a2, a3, b0A, b1A);
                mma16(acc[df2*2+1], a0, a1, a2, a3, b0B, b1B);
            }
        }
    }

    // ---- merge the two groups' partial softmax states ----
    float* macc = (float*)sm;              // [64][132]
    float* marr = (float*)sm + 33792/4 * 4 / 4;  // placeholder; computed below
    marr = (float*)(sm + 33792);           // [64]
    float* larr = (float*)(sm + 34048);    // [64]

    const int r0 = wl*16 + quad;
    const int r1 = r0 + 8;

    __syncthreads();   // both groups done with their rings
    if (wg == 1) {
        #pragma unroll
        for (int nt = 0; nt < 16; nt++) {
            int c0 = nt*8 + qt*2;
            *(float2*)(macc + r0*132 + c0) = make_float2(acc[nt][0], acc[nt][1]);
            *(float2*)(macc + r1*132 + c0) = make_float2(acc[nt][2], acc[nt][3]);
        }
        if (qt == 0) {
            marr[r0] = m0; marr[r1] = m1;
            larr[r0] = l0; larr[r1] = l1;
        }
    }
    __syncthreads();
    if (wg == 0) {
        float mB0 = marr[r0], mB1 = marr[r1];
        float lB0 = larr[r0], lB1 = larr[r1];
        float mn0 = fmaxf(m0, mB0), mn1 = fmaxf(m1, mB1);
        float fA0 = exp2f(m0 - mn0), fB0 = exp2f(mB0 - mn0);
        float fA1 = exp2f(m1 - mn1), fB1 = exp2f(mB1 - mn1);
        float inv0 = 1.0f / (l0*fA0 + lB0*fB0);
        float inv1 = 1.0f / (l1*fA1 + lB1*fB1);

        int s0 = qb*64 + r0;
        int s1 = qb*64 + r1;
        __half* o0 = g_flath + ((size_t)b*SEQ + s0)*(HEADS*UNITS) + h*UNITS;
        __half* o1 = g_flath + ((size_t)b*SEQ + s1)*(HEADS*UNITS) + h*UNITS;
        #pragma unroll
        for (int nt = 0; nt < 16; nt++) {
            int c0 = nt*8 + qt*2;
            float2 vb0 = *(float2*)(macc + r0*132 + c0);
            float2 vb1 = *(float2*)(macc + r1*132 + c0);
            *(uint32_t*)(o0 + c0) = pack_h2((acc[nt][0]*fA0 + vb0.x*fB0)*inv0,
                                            (acc[nt][1]*fA0 + vb0.y*fB0)*inv0);
            *(uint32_t*)(o1 + c0) = pack_h2((acc[nt][2]*fA1 + vb1.x*fB1)*inv1,
                                            (acc[nt][3]*fA1 + vb1.y*fB1)*inv1);
        }
    }
}

// ---------------------------------------------------------------------------
extern "C" void kernel_launch(void* const* d_in, const int* in_sizes, int n_in,
                              void* d_out, int out_size)
{
    (void)in_sizes; (void)n_in; (void)out_size;
    const float* x   = (const float*)d_in[0];
    const float* wq  = (const float*)d_in[1];
    const float* wk  = (const float*)d_in[2];
    const float* wv  = (const float*)d_in[3];
    const float* bq  = (const float*)d_in[4];
    const float* bk  = (const float*)d_in[5];
    const float* bv  = (const float*)d_in[6];
    const float* wh  = (const float*)d_in[7];
    const float* bh  = (const float*)d_in[8];
    float* out = (float*)d_out;

    const int gemm4_smem = 2 * (128 + 128) * 144;   // 73728
    const int gemm2_smem = 2 * (64 + 128) * 144;    // 55296
    const int attn_smem  = 2 * 69632;               // 139264
    cudaFuncSetAttribute(gemm_h_kernel<4>, cudaFuncAttributeMaxDynamicSharedMemorySize, gemm4_smem);
    cudaFuncSetAttribute(gemm_h_kernel<2>, cudaFuncAttributeMaxDynamicSharedMemorySize, gemm2_smem);
    cudaFuncSetAttribute(attn_h_kernel,    cudaFuncAttributeMaxDynamicSharedMemorySize, attn_smem);

    convert_x_kernel<<<(BATCH*SEQ*DIN)/(256*4), 256>>>(x);
    transpose_w_kernel<<<dim3(32, 4, 25), dim3(32, 8)>>>(wq, wk, wv, wh);
    gemm_h_kernel<4><<<dim3(64, 24), 256, gemm4_smem>>>(0, bq, bk, bv, bh, nullptr);
    attn_h_kernel<<<dim3(32, 32), 256, attn_smem>>>();
    gemm_h_kernel<2><<<dim3(128, 1), 256, gemm2_smem>>>(1, bq, bk, bv, bh, out);
}